// round 1
// baseline (speedup 1.0000x reference)
#include <cuda_runtime.h>
#include <math.h>

#define NTOK 8192      // B*S
#define DIM  1024      // d_model
#define NE   8         // experts
#define TOPK 2
#define HID  4096      // expert hidden
#define NA   (NTOK*TOPK)   // 16384 assignments
#define CAP  NA            // per-expert bucket capacity (worst case)

// ---------------- device scratch (no allocations allowed) ----------------
__device__ int   g_bucket[NE*CAP];     // assignment ids per expert
__device__ int   g_cursor[NE];         // per-expert count (atomic cursor)
__device__ float g_prob_sum[NE];       // sum of router probs per expert
__device__ float g_topk_w[NA];         // combine weight per assignment
__device__ float g_h[(size_t)NA*HID];  // up-proj activations (268 MB)
__device__ float g_y[(size_t)NA*DIM];  // down-proj outputs   (67 MB)

// ---------------- kernel 1: zero accumulators ----------------
__global__ void zero_kernel() {
    int t = threadIdx.x;
    if (t < NE) { g_cursor[t] = 0; g_prob_sum[t] = 0.f; }
}

// ---------------- kernel 2: router ----------------
// 1 block per token, 256 threads. Computes logits, full softmax (-> probs out),
// top-2 indices + top-2 softmax weights, fills per-expert buckets.
__global__ __launch_bounds__(256) void router_kernel(
    const float* __restrict__ x, const float* __restrict__ rw,
    const float* __restrict__ rb, float* __restrict__ probs_out)
{
    int t   = blockIdx.x;
    int tid = threadIdx.x;
    const float* xr = x + (size_t)t * DIM;

    float acc[NE];
    #pragma unroll
    for (int e = 0; e < NE; e++) acc[e] = 0.f;

    for (int d = tid; d < DIM; d += 256) {
        float xv = xr[d];
        const float* w = rw + (size_t)d * NE;
        #pragma unroll
        for (int e = 0; e < NE; e++) acc[e] += xv * w[e];
    }
    // warp reduce
    #pragma unroll
    for (int e = 0; e < NE; e++) {
        #pragma unroll
        for (int off = 16; off > 0; off >>= 1)
            acc[e] += __shfl_down_sync(0xffffffffu, acc[e], off);
    }
    __shared__ float wsum[8][NE];
    int warp = tid >> 5, lane = tid & 31;
    if (lane == 0) {
        #pragma unroll
        for (int e = 0; e < NE; e++) wsum[warp][e] = acc[e];
    }
    __syncthreads();

    if (tid == 0) {
        float lg[NE];
        #pragma unroll
        for (int e = 0; e < NE; e++) {
            float s = rb[e];
            #pragma unroll
            for (int w = 0; w < 8; w++) s += wsum[w][e];
            lg[e] = s;
        }
        // full softmax -> probs
        float mx = lg[0];
        #pragma unroll
        for (int e = 1; e < NE; e++) mx = fmaxf(mx, lg[e]);
        float p[NE], den = 0.f;
        #pragma unroll
        for (int e = 0; e < NE; e++) { p[e] = expf(lg[e] - mx); den += p[e]; }
        float inv = 1.f / den;
        #pragma unroll
        for (int e = 0; e < NE; e++) {
            p[e] *= inv;
            probs_out[(size_t)t * NE + e] = p[e];
            atomicAdd(&g_prob_sum[e], p[e]);
        }
        // top-2 (first index wins ties, matching lax.top_k)
        int i0 = 0;
        #pragma unroll
        for (int e = 1; e < NE; e++) if (lg[e] > lg[i0]) i0 = e;
        int i1 = -1;
        #pragma unroll
        for (int e = 0; e < NE; e++)
            if (e != i0 && (i1 < 0 || lg[e] > lg[i1])) i1 = e;
        // softmax over the 2 selected logits
        float e1 = expf(lg[i1] - lg[i0]);
        float p0 = 1.f / (1.f + e1);
        float p1 = e1 * p0;

        int a0 = t * TOPK + 0, a1 = t * TOPK + 1;
        g_topk_w[a0] = p0;
        g_topk_w[a1] = p1;
        int s0 = atomicAdd(&g_cursor[i0], 1);
        g_bucket[i0 * CAP + s0] = a0;
        int s1 = atomicAdd(&g_cursor[i1], 1);
        g_bucket[i1 * CAP + s1] = a1;
    }
}

// ---------------- kernel 3: aux loss ----------------
__global__ void aux_kernel(float* __restrict__ out_aux) {
    if (threadIdx.x == 0) {
        float s = 0.f;
        #pragma unroll
        for (int e = 0; e < NE; e++)
            s += ((float)g_cursor[e] / (float)NA) * (g_prob_sum[e] / (float)NTOK);
        *out_aux = (float)NE * s * 0.01f;
    }
}

// ---------------- grouped SGEMM tiles ----------------
#define TM 128
#define TN 128
#define TK 16

__device__ __forceinline__ float gelu_tanh(float v) {
    float c = v * v * v;
    return 0.5f * v * (1.f + tanhf(0.7978845608028654f * (v + 0.044715f * c)));
}

// Up projection: A = gathered x rows (per-expert bucket), B = w_up[e] (D x H)
// C = gelu(A@B + b_up[e]) scattered into g_h by assignment id.
__global__ __launch_bounds__(256) void up_kernel(
    const float* __restrict__ x, const float* __restrict__ wup,
    const float* __restrict__ bup)
{
    int e   = blockIdx.z;
    int cnt = g_cursor[e];
    int m0  = blockIdx.y * TM;
    if (m0 >= cnt) return;
    int n0  = blockIdx.x * TN;

    __shared__ float As[TK][TM];
    __shared__ float Bs[TK][TN];
    __shared__ int   rows[TM];

    int tid = threadIdx.x;
    for (int i = tid; i < TM; i += 256) {
        int m = m0 + i;
        rows[i] = (m < cnt) ? g_bucket[e * CAP + m] : -1;
    }
    __syncthreads();

    int tx = tid & 15;   // n
    int ty = tid >> 4;   // m
    float acc[8][8];
    #pragma unroll
    for (int i = 0; i < 8; i++)
        #pragma unroll
        for (int j = 0; j < 8; j++) acc[i][j] = 0.f;

    const float* wB = wup + (size_t)e * DIM * HID;

    for (int kt = 0; kt < DIM; kt += TK) {
        // A tile: 128 rows x 16 k (gathered, transposed into As[k][m])
        #pragma unroll
        for (int it = 0; it < 2; it++) {
            int idx = tid * 2 + it;          // 0..511
            int r   = idx >> 2;              // 0..127
            int kq  = idx & 3;               // 0..3 (float4 within k)
            int a   = rows[r];
            float4 v = make_float4(0.f, 0.f, 0.f, 0.f);
            if (a >= 0)
                v = *(const float4*)(x + (size_t)(a >> 1) * DIM + kt + kq * 4);
            As[kq*4+0][r] = v.x; As[kq*4+1][r] = v.y;
            As[kq*4+2][r] = v.z; As[kq*4+3][r] = v.w;
        }
        // B tile: 16 k x 128 n
        #pragma unroll
        for (int it = 0; it < 2; it++) {
            int idx = tid * 2 + it;
            int k   = idx >> 5;              // 0..15
            int nq  = idx & 31;              // 0..31
            float4 v = *(const float4*)(wB + (size_t)(kt + k) * HID + n0 + nq * 4);
            *(float4*)&Bs[k][nq * 4] = v;
        }
        __syncthreads();
        #pragma unroll
        for (int kk = 0; kk < TK; kk++) {
            float4 a0 = *(float4*)&As[kk][ty * 8];
            float4 a1 = *(float4*)&As[kk][ty * 8 + 4];
            float4 b0 = *(float4*)&Bs[kk][tx * 8];
            float4 b1 = *(float4*)&Bs[kk][tx * 8 + 4];
            float av[8] = {a0.x,a0.y,a0.z,a0.w,a1.x,a1.y,a1.z,a1.w};
            float bv[8] = {b0.x,b0.y,b0.z,b0.w,b1.x,b1.y,b1.z,b1.w};
            #pragma unroll
            for (int i = 0; i < 8; i++)
                #pragma unroll
                for (int j = 0; j < 8; j++) acc[i][j] += av[i] * bv[j];
        }
        __syncthreads();
    }

    const float* bb = bup + (size_t)e * HID + n0;
    #pragma unroll
    for (int i = 0; i < 8; i++) {
        int a = rows[ty * 8 + i];
        if (a < 0) continue;
        float* hrow = g_h + (size_t)a * HID + n0;
        #pragma unroll
        for (int j = 0; j < 8; j++) {
            float v = acc[i][j] + bb[tx * 8 + j];
            hrow[tx * 8 + j] = gelu_tanh(v);
        }
    }
}

// Down projection: A = gathered g_h rows, B = w_down[e] (H x D)
// C = A@B + b_down[e] scattered into g_y by assignment id.
__global__ __launch_bounds__(256) void down_kernel(
    const float* __restrict__ wdn, const float* __restrict__ bdn)
{
    int e   = blockIdx.z;
    int cnt = g_cursor[e];
    int m0  = blockIdx.y * TM;
    if (m0 >= cnt) return;
    int n0  = blockIdx.x * TN;

    __shared__ float As[TK][TM];
    __shared__ float Bs[TK][TN];
    __shared__ int   rows[TM];

    int tid = threadIdx.x;
    for (int i = tid; i < TM; i += 256) {
        int m = m0 + i;
        rows[i] = (m < cnt) ? g_bucket[e * CAP + m] : -1;
    }
    __syncthreads();

    int tx = tid & 15;
    int ty = tid >> 4;
    float acc[8][8];
    #pragma unroll
    for (int i = 0; i < 8; i++)
        #pragma unroll
        for (int j = 0; j < 8; j++) acc[i][j] = 0.f;

    const float* wB = wdn + (size_t)e * HID * DIM;

    for (int kt = 0; kt < HID; kt += TK) {
        #pragma unroll
        for (int it = 0; it < 2; it++) {
            int idx = tid * 2 + it;
            int r   = idx >> 2;
            int kq  = idx & 3;
            int a   = rows[r];
            float4 v = make_float4(0.f, 0.f, 0.f, 0.f);
            if (a >= 0)
                v = *(const float4*)(g_h + (size_t)a * HID + kt + kq * 4);
            As[kq*4+0][r] = v.x; As[kq*4+1][r] = v.y;
            As[kq*4+2][r] = v.z; As[kq*4+3][r] = v.w;
        }
        #pragma unroll
        for (int it = 0; it < 2; it++) {
            int idx = tid * 2 + it;
            int k   = idx >> 5;
            int nq  = idx & 31;
            float4 v = *(const float4*)(wB + (size_t)(kt + k) * DIM + n0 + nq * 4);
            *(float4*)&Bs[k][nq * 4] = v;
        }
        __syncthreads();
        #pragma unroll
        for (int kk = 0; kk < TK; kk++) {
            float4 a0 = *(float4*)&As[kk][ty * 8];
            float4 a1 = *(float4*)&As[kk][ty * 8 + 4];
            float4 b0 = *(float4*)&Bs[kk][tx * 8];
            float4 b1 = *(float4*)&Bs[kk][tx * 8 + 4];
            float av[8] = {a0.x,a0.y,a0.z,a0.w,a1.x,a1.y,a1.z,a1.w};
            float bv[8] = {b0.x,b0.y,b0.z,b0.w,b1.x,b1.y,b1.z,b1.w};
            #pragma unroll
            for (int i = 0; i < 8; i++)
                #pragma unroll
                for (int j = 0; j < 8; j++) acc[i][j] += av[i] * bv[j];
        }
        __syncthreads();
    }

    const float* bb = bdn + (size_t)e * DIM + n0;
    #pragma unroll
    for (int i = 0; i < 8; i++) {
        int a = rows[ty * 8 + i];
        if (a < 0) continue;
        float* yrow = g_y + (size_t)a * DIM + n0;
        #pragma unroll
        for (int j = 0; j < 8; j++)
            yrow[tx * 8 + j] = acc[i][j] + bb[tx * 8 + j];
    }
}

// ---------------- kernel 6: deterministic weighted combine ----------------
__global__ __launch_bounds__(256) void combine_kernel(float* __restrict__ out) {
    int t = blockIdx.x;
    float w0 = g_topk_w[t * TOPK + 0];
    float w1 = g_topk_w[t * TOPK + 1];
    const float4* y0 = (const float4*)(g_y + (size_t)(t * TOPK + 0) * DIM);
    const float4* y1 = (const float4*)(g_y + (size_t)(t * TOPK + 1) * DIM);
    float4* o = (float4*)(out + (size_t)t * DIM);
    for (int d = threadIdx.x; d < DIM / 4; d += 256) {
        float4 a = y0[d], b = y1[d];
        float4 r;
        r.x = w0 * a.x + w1 * b.x;
        r.y = w0 * a.y + w1 * b.y;
        r.z = w0 * a.z + w1 * b.z;
        r.w = w0 * a.w + w1 * b.w;
        o[d] = r;
    }
}

// ---------------- launch ----------------
extern "C" void kernel_launch(void* const* d_in, const int* in_sizes, int n_in,
                              void* d_out, int out_size)
{
    const float* x  = (const float*)d_in[0];
    const float* rw = (const float*)d_in[1];
    const float* rb = (const float*)d_in[2];
    const float* wu = (const float*)d_in[3];
    const float* bu = (const float*)d_in[4];
    const float* wd = (const float*)d_in[5];
    const float* bd = (const float*)d_in[6];

    float* out       = (float*)d_out;
    float* out_y     = out;                              // (B,S,D)
    float* out_aux   = out + (size_t)NTOK * DIM;         // scalar
    float* out_probs = out_aux + 1;                      // (B,S,E)

    zero_kernel<<<1, 32>>>();
    router_kernel<<<NTOK, 256>>>(x, rw, rb, out_probs);
    aux_kernel<<<1, 32>>>(out_aux);

    dim3 gu(HID / TN, CAP / TM, NE);   // (32, 128, 8) — most m-tiles early-exit
    up_kernel<<<gu, 256>>>(x, wu, bu);

    dim3 gd(DIM / TN, CAP / TM, NE);   // (8, 128, 8)
    down_kernel<<<gd, 256>>>(wd, bd);

    combine_kernel<<<NTOK, 256>>>(out_y);
}

// round 2
// speedup vs baseline: 3.1633x; 3.1633x over previous
#include <cuda_runtime.h>
#include <math.h>
#include <cstdint>

#define NTOK 8192      // B*S
#define DIM  1024      // d_model
#define NE   8         // experts
#define TOPK 2
#define HID  4096      // expert hidden
#define NA   (NTOK*TOPK)   // 16384 assignments
#define CAP  NA            // per-expert bucket capacity (worst case)

// ---------------- device scratch (no allocations allowed) ----------------
__device__ int   g_bucket[NE*CAP];
__device__ int   g_cursor[NE];
__device__ float g_prob_sum[NE];
__device__ float g_topk_w[NA];
__device__ float g_h[(size_t)NA*HID];  // up-proj activations (268 MB)
__device__ float g_y[(size_t)NA*DIM];  // down-proj outputs   (67 MB)

// ---------------- kernel 1: zero accumulators ----------------
__global__ void zero_kernel() {
    int t = threadIdx.x;
    if (t < NE) { g_cursor[t] = 0; g_prob_sum[t] = 0.f; }
}

// ---------------- kernel 2: router ----------------
__global__ __launch_bounds__(256) void router_kernel(
    const float* __restrict__ x, const float* __restrict__ rw,
    const float* __restrict__ rb, float* __restrict__ probs_out)
{
    int t   = blockIdx.x;
    int tid = threadIdx.x;
    const float* xr = x + (size_t)t * DIM;

    float acc[NE];
    #pragma unroll
    for (int e = 0; e < NE; e++) acc[e] = 0.f;

    for (int d = tid; d < DIM; d += 256) {
        float xv = xr[d];
        const float* w = rw + (size_t)d * NE;
        #pragma unroll
        for (int e = 0; e < NE; e++) acc[e] += xv * w[e];
    }
    #pragma unroll
    for (int e = 0; e < NE; e++) {
        #pragma unroll
        for (int off = 16; off > 0; off >>= 1)
            acc[e] += __shfl_down_sync(0xffffffffu, acc[e], off);
    }
    __shared__ float wsum[8][NE];
    int warp = tid >> 5, lane = tid & 31;
    if (lane == 0) {
        #pragma unroll
        for (int e = 0; e < NE; e++) wsum[warp][e] = acc[e];
    }
    __syncthreads();

    if (tid == 0) {
        float lg[NE];
        #pragma unroll
        for (int e = 0; e < NE; e++) {
            float s = rb[e];
            #pragma unroll
            for (int w = 0; w < 8; w++) s += wsum[w][e];
            lg[e] = s;
        }
        float mx = lg[0];
        #pragma unroll
        for (int e = 1; e < NE; e++) mx = fmaxf(mx, lg[e]);
        float p[NE], den = 0.f;
        #pragma unroll
        for (int e = 0; e < NE; e++) { p[e] = expf(lg[e] - mx); den += p[e]; }
        float inv = 1.f / den;
        #pragma unroll
        for (int e = 0; e < NE; e++) {
            p[e] *= inv;
            probs_out[(size_t)t * NE + e] = p[e];
            atomicAdd(&g_prob_sum[e], p[e]);
        }
        int i0 = 0;
        #pragma unroll
        for (int e = 1; e < NE; e++) if (lg[e] > lg[i0]) i0 = e;
        int i1 = -1;
        #pragma unroll
        for (int e = 0; e < NE; e++)
            if (e != i0 && (i1 < 0 || lg[e] > lg[i1])) i1 = e;
        float e1 = expf(lg[i1] - lg[i0]);
        float p0 = 1.f / (1.f + e1);
        float p1 = e1 * p0;

        int a0 = t * TOPK + 0, a1 = t * TOPK + 1;
        g_topk_w[a0] = p0;
        g_topk_w[a1] = p1;
        int s0 = atomicAdd(&g_cursor[i0], 1);
        g_bucket[i0 * CAP + s0] = a0;
        int s1 = atomicAdd(&g_cursor[i1], 1);
        g_bucket[i1 * CAP + s1] = a1;
    }
}

// ---------------- kernel 3: aux loss ----------------
__global__ void aux_kernel(float* __restrict__ out_aux) {
    if (threadIdx.x == 0) {
        float s = 0.f;
        #pragma unroll
        for (int e = 0; e < NE; e++)
            s += ((float)g_cursor[e] / (float)NA) * (g_prob_sum[e] / (float)NTOK);
        *out_aux = (float)NE * s * 0.01f;
    }
}

// ---------------- tensor-core grouped GEMM ----------------
#define TM 128
#define TN 128
#define TKK 32
#define STAGES 3
#define A_STRIDE (TKK+4)     // A tile [m][k], padded
#define B_STRIDE (TN+4)      // B tile [k][n], padded
#define SMEM_FLOATS (STAGES*(TM*A_STRIDE + TKK*B_STRIDE))
#define SMEM_BYTES (SMEM_FLOATS*4 + TM*4)

__device__ __forceinline__ float gelu_tanh(float v) {
    float c = v * v * v;
    return 0.5f * v * (1.f + tanhf(0.7978845608028654f * (v + 0.044715f * c)));
}

__device__ __forceinline__ uint32_t f2tf32(float f) {
    uint32_t r;
    asm("cvt.rna.tf32.f32 %0, %1;" : "=r"(r) : "f"(f));
    return r;
}

__device__ __forceinline__ void mma_tf32(float* c, const uint32_t* a, const uint32_t* b) {
    asm volatile(
        "mma.sync.aligned.m16n8k8.row.col.f32.tf32.tf32.f32 "
        "{%0,%1,%2,%3}, {%4,%5,%6,%7}, {%8,%9}, {%0,%1,%2,%3};"
        : "+f"(c[0]), "+f"(c[1]), "+f"(c[2]), "+f"(c[3])
        : "r"(a[0]), "r"(a[1]), "r"(a[2]), "r"(a[3]), "r"(b[0]), "r"(b[1]));
}

__device__ __forceinline__ void cp_async16(float* dst, const float* src, bool pred) {
    uint32_t d = (uint32_t)__cvta_generic_to_shared(dst);
    int sz = pred ? 16 : 0;
    asm volatile("cp.async.cg.shared.global [%0], [%1], 16, %2;\n"
                 :: "r"(d), "l"(src), "r"(sz));
}

// UP:  A = gathered x rows,   W = w_up[e]  (DIM x HID), epilogue = gelu -> g_h
// DN:  A = gathered g_h rows, W = w_down[e](HID x DIM), epilogue = +bias -> g_y
template<bool UP>
__global__ __launch_bounds__(128)
void mma_gemm_kernel(const float* __restrict__ x,
                     const float* __restrict__ Wall,
                     const float* __restrict__ Ball)
{
    constexpr int KD = UP ? DIM : HID;
    constexpr int ND = UP ? HID : DIM;
    constexpr int KT = KD / TKK;

    int e   = blockIdx.z;
    int cnt = g_cursor[e];
    int m0  = blockIdx.y * TM;
    if (m0 >= cnt) return;
    int n0  = blockIdx.x * TN;

    extern __shared__ float smem[];
    float* As = smem;                                   // [STAGES][TM][A_STRIDE]
    float* Bs = smem + STAGES * TM * A_STRIDE;          // [STAGES][TKK][B_STRIDE]
    int*  rows = (int*)(Bs + STAGES * TKK * B_STRIDE);  // [TM]

    int tid = threadIdx.x;
    for (int i = tid; i < TM; i += 128) {
        int m = m0 + i;
        rows[i] = (m < cnt) ? g_bucket[e * CAP + m] : -1;
    }
    __syncthreads();

    const float* W = Wall + (size_t)e * KD * ND;
    const float* hbase = (const float*)g_h;

    auto issue = [&](int kt, int stage) {
        float* as = As + stage * TM * A_STRIDE;
        float* bs = Bs + stage * TKK * B_STRIDE;
        int kbase = kt * TKK;
        #pragma unroll
        for (int i = 0; i < 8; i++) {
            int c = tid + i * 128;
            int r = c >> 3, q = c & 7;      // 128 rows x 8 float4 chunks
            int a = rows[r];
            bool pred = (a >= 0);
            const float* src;
            if (UP) src = x + (size_t)(pred ? (a >> 1) : 0) * DIM + kbase + q * 4;
            else    src = hbase + (size_t)(pred ? a : 0) * HID + kbase + q * 4;
            cp_async16(as + r * A_STRIDE + q * 4, src, pred);
        }
        #pragma unroll
        for (int i = 0; i < 8; i++) {
            int c = tid + i * 128;
            int k = c >> 5, q = c & 31;     // 32 k-rows x 32 float4 chunks
            cp_async16(bs + k * B_STRIDE + q * 4,
                       W + (size_t)(kbase + k) * ND + n0 + q * 4, true);
        }
    };

    // prologue: fill STAGES-1 stages
    #pragma unroll
    for (int s = 0; s < STAGES - 1; s++) {
        if (s < KT) issue(s, s);
        asm volatile("cp.async.commit_group;");
    }

    int wid = tid >> 5, lane = tid & 31;
    int g = lane >> 2, t = lane & 3;
    int wm = (wid >> 1) * 64;   // warp m offset (2x2 warp grid, 64x64 tiles)
    int wn = (wid & 1) * 64;

    float acc[4][8][4];
    #pragma unroll
    for (int i = 0; i < 4; i++)
        #pragma unroll
        for (int j = 0; j < 8; j++)
            #pragma unroll
            for (int q = 0; q < 4; q++) acc[i][j][q] = 0.f;

    for (int kt = 0; kt < KT; kt++) {
        asm volatile("cp.async.wait_group %0;" :: "n"(STAGES - 2));
        __syncthreads();

        int nstage = kt + STAGES - 1;
        if (nstage < KT) issue(nstage, nstage % STAGES);
        asm volatile("cp.async.commit_group;");

        const float* as = As + (kt % STAGES) * TM * A_STRIDE;
        const float* bs = Bs + (kt % STAGES) * TKK * B_STRIDE;

        #pragma unroll
        for (int k8 = 0; k8 < TKK / 8; k8++) {
            uint32_t af[4][4], bf[8][2];
            #pragma unroll
            for (int i = 0; i < 4; i++) {
                int mrow = wm + i * 16;
                af[i][0] = f2tf32(as[(mrow + g    ) * A_STRIDE + k8 * 8 + t]);
                af[i][1] = f2tf32(as[(mrow + g + 8) * A_STRIDE + k8 * 8 + t]);
                af[i][2] = f2tf32(as[(mrow + g    ) * A_STRIDE + k8 * 8 + t + 4]);
                af[i][3] = f2tf32(as[(mrow + g + 8) * A_STRIDE + k8 * 8 + t + 4]);
            }
            #pragma unroll
            for (int j = 0; j < 8; j++) {
                int ncol = wn + j * 8 + g;
                bf[j][0] = f2tf32(bs[(k8 * 8 + t    ) * B_STRIDE + ncol]);
                bf[j][1] = f2tf32(bs[(k8 * 8 + t + 4) * B_STRIDE + ncol]);
            }
            #pragma unroll
            for (int i = 0; i < 4; i++)
                #pragma unroll
                for (int j = 0; j < 8; j++)
                    mma_tf32(acc[i][j], af[i], bf[j]);
        }
    }

    // epilogue: bias (+gelu) and scatter by assignment id
    const float* bb = Ball + (size_t)e * ND + n0;
    #pragma unroll
    for (int i = 0; i < 4; i++) {
        int r0 = wm + i * 16 + g;
        int r1 = r0 + 8;
        int a0 = rows[r0], a1 = rows[r1];
        float* d0 = (a0 >= 0) ? ((UP ? g_h + (size_t)a0 * HID : g_y + (size_t)a0 * DIM) + n0) : nullptr;
        float* d1 = (a1 >= 0) ? ((UP ? g_h + (size_t)a1 * HID : g_y + (size_t)a1 * DIM) + n0) : nullptr;
        #pragma unroll
        for (int j = 0; j < 8; j++) {
            int col = wn + j * 8 + t * 2;
            float bx = bb[col], by = bb[col + 1];
            if (d0) {
                float v0 = acc[i][j][0] + bx, v1 = acc[i][j][1] + by;
                if (UP) { v0 = gelu_tanh(v0); v1 = gelu_tanh(v1); }
                *(float2*)(d0 + col) = make_float2(v0, v1);
            }
            if (d1) {
                float v2 = acc[i][j][2] + bx, v3 = acc[i][j][3] + by;
                if (UP) { v2 = gelu_tanh(v2); v3 = gelu_tanh(v3); }
                *(float2*)(d1 + col) = make_float2(v2, v3);
            }
        }
    }
}

// ---------------- kernel 6: deterministic weighted combine ----------------
__global__ __launch_bounds__(256) void combine_kernel(float* __restrict__ out) {
    int t = blockIdx.x;
    float w0 = g_topk_w[t * TOPK + 0];
    float w1 = g_topk_w[t * TOPK + 1];
    const float4* y0 = (const float4*)(g_y + (size_t)(t * TOPK + 0) * DIM);
    const float4* y1 = (const float4*)(g_y + (size_t)(t * TOPK + 1) * DIM);
    float4* o = (float4*)(out + (size_t)t * DIM);
    for (int d = threadIdx.x; d < DIM / 4; d += 256) {
        float4 a = y0[d], b = y1[d];
        float4 r;
        r.x = w0 * a.x + w1 * b.x;
        r.y = w0 * a.y + w1 * b.y;
        r.z = w0 * a.z + w1 * b.z;
        r.w = w0 * a.w + w1 * b.w;
        o[d] = r;
    }
}

// ---------------- launch ----------------
extern "C" void kernel_launch(void* const* d_in, const int* in_sizes, int n_in,
                              void* d_out, int out_size)
{
    const float* x  = (const float*)d_in[0];
    const float* rw = (const float*)d_in[1];
    const float* rb = (const float*)d_in[2];
    const float* wu = (const float*)d_in[3];
    const float* bu = (const float*)d_in[4];
    const float* wd = (const float*)d_in[5];
    const float* bd = (const float*)d_in[6];

    float* out       = (float*)d_out;
    float* out_y     = out;
    float* out_aux   = out + (size_t)NTOK * DIM;
    float* out_probs = out_aux + 1;

    cudaFuncSetAttribute(mma_gemm_kernel<true>,
        cudaFuncAttributeMaxDynamicSharedMemorySize, SMEM_BYTES);
    cudaFuncSetAttribute(mma_gemm_kernel<false>,
        cudaFuncAttributeMaxDynamicSharedMemorySize, SMEM_BYTES);

    zero_kernel<<<1, 32>>>();
    router_kernel<<<NTOK, 256>>>(x, rw, rb, out_probs);
    aux_kernel<<<1, 32>>>(out_aux);

    dim3 gu(HID / TN, CAP / TM, NE);
    mma_gemm_kernel<true><<<gu, 128, SMEM_BYTES>>>(x, wu, bu);

    dim3 gd(DIM / TN, CAP / TM, NE);
    mma_gemm_kernel<false><<<gd, 128, SMEM_BYTES>>>(x, wd, bd);

    combine_kernel<<<NTOK, 256>>>(out_y);
}

// round 3
// speedup vs baseline: 3.5488x; 1.1219x over previous
#include <cuda_runtime.h>
#include <math.h>
#include <cstdint>

#define NTOK 8192      // B*S
#define DIM  1024      // d_model
#define NE   8         // experts
#define TOPK 2
#define HID  4096      // expert hidden
#define NA   (NTOK*TOPK)   // 16384 assignments
#define CAP  NA            // per-expert bucket capacity (worst case)

// ---------------- device scratch (no allocations allowed) ----------------
__device__ int   g_bucket[NE*CAP];
__device__ int   g_cursor[NE];
__device__ float g_prob_sum[NE];
__device__ float g_topk_w[NA];
__device__ float g_h[(size_t)NA*HID];       // up-proj activations (268 MB), tf32-rounded
__device__ float g_y[(size_t)NA*DIM];       // down-proj outputs   (67 MB)
__device__ float g_xr[(size_t)NTOK*DIM];    // tf32-rounded x      (33 MB)
__device__ float g_wur[(size_t)NE*DIM*HID]; // tf32-rounded w_up   (134 MB)
__device__ float g_wdr[(size_t)NE*HID*DIM]; // tf32-rounded w_down (134 MB)

__device__ __forceinline__ uint32_t f2tf32(float f) {
    uint32_t r;
    asm("cvt.rna.tf32.f32 %0, %1;" : "=r"(r) : "f"(f));
    return r;
}

// ---------------- tf32 pre-round (one cvt per element, outside GEMM) ------
__global__ __launch_bounds__(256) void round_kernel(
    const float4* __restrict__ src, float4* __restrict__ dst, int n4)
{
    int stride = gridDim.x * blockDim.x;
    for (int i = blockIdx.x * blockDim.x + threadIdx.x; i < n4; i += stride) {
        float4 v = src[i];
        v.x = __uint_as_float(f2tf32(v.x));
        v.y = __uint_as_float(f2tf32(v.y));
        v.z = __uint_as_float(f2tf32(v.z));
        v.w = __uint_as_float(f2tf32(v.w));
        dst[i] = v;
    }
}

// ---------------- kernel 1: zero accumulators ----------------
__global__ void zero_kernel() {
    int t = threadIdx.x;
    if (t < NE) { g_cursor[t] = 0; g_prob_sum[t] = 0.f; }
}

// ---------------- kernel 2: router ----------------
__global__ __launch_bounds__(256) void router_kernel(
    const float* __restrict__ x, const float* __restrict__ rw,
    const float* __restrict__ rb, float* __restrict__ probs_out)
{
    int t   = blockIdx.x;
    int tid = threadIdx.x;
    const float* xr = x + (size_t)t * DIM;

    float acc[NE];
    #pragma unroll
    for (int e = 0; e < NE; e++) acc[e] = 0.f;

    for (int d = tid; d < DIM; d += 256) {
        float xv = xr[d];
        const float* w = rw + (size_t)d * NE;
        #pragma unroll
        for (int e = 0; e < NE; e++) acc[e] += xv * w[e];
    }
    #pragma unroll
    for (int e = 0; e < NE; e++) {
        #pragma unroll
        for (int off = 16; off > 0; off >>= 1)
            acc[e] += __shfl_down_sync(0xffffffffu, acc[e], off);
    }
    __shared__ float wsum[8][NE];
    int warp = tid >> 5, lane = tid & 31;
    if (lane == 0) {
        #pragma unroll
        for (int e = 0; e < NE; e++) wsum[warp][e] = acc[e];
    }
    __syncthreads();

    if (tid == 0) {
        float lg[NE];
        #pragma unroll
        for (int e = 0; e < NE; e++) {
            float s = rb[e];
            #pragma unroll
            for (int w = 0; w < 8; w++) s += wsum[w][e];
            lg[e] = s;
        }
        float mx = lg[0];
        #pragma unroll
        for (int e = 1; e < NE; e++) mx = fmaxf(mx, lg[e]);
        float p[NE], den = 0.f;
        #pragma unroll
        for (int e = 0; e < NE; e++) { p[e] = expf(lg[e] - mx); den += p[e]; }
        float inv = 1.f / den;
        #pragma unroll
        for (int e = 0; e < NE; e++) {
            p[e] *= inv;
            probs_out[(size_t)t * NE + e] = p[e];
            atomicAdd(&g_prob_sum[e], p[e]);
        }
        int i0 = 0;
        #pragma unroll
        for (int e = 1; e < NE; e++) if (lg[e] > lg[i0]) i0 = e;
        int i1 = -1;
        #pragma unroll
        for (int e = 0; e < NE; e++)
            if (e != i0 && (i1 < 0 || lg[e] > lg[i1])) i1 = e;
        float e1 = expf(lg[i1] - lg[i0]);
        float p0 = 1.f / (1.f + e1);
        float p1 = e1 * p0;

        int a0 = t * TOPK + 0, a1 = t * TOPK + 1;
        g_topk_w[a0] = p0;
        g_topk_w[a1] = p1;
        int s0 = atomicAdd(&g_cursor[i0], 1);
        g_bucket[i0 * CAP + s0] = a0;
        int s1 = atomicAdd(&g_cursor[i1], 1);
        g_bucket[i1 * CAP + s1] = a1;
    }
}

// ---------------- kernel 3: aux loss ----------------
__global__ void aux_kernel(float* __restrict__ out_aux) {
    if (threadIdx.x == 0) {
        float s = 0.f;
        #pragma unroll
        for (int e = 0; e < NE; e++)
            s += ((float)g_cursor[e] / (float)NA) * (g_prob_sum[e] / (float)NTOK);
        *out_aux = (float)NE * s * 0.01f;
    }
}

// ---------------- tensor-core grouped GEMM ----------------
#define TM 128
#define TN 128
#define TKK 32
#define STAGES 3
#define A_STRIDE (TKK+4)     // A tile [m][k], padded (banks 4g+t: conflict-free)
#define B_STRIDE (TN+8)      // B tile [k][n], padded (banks 8t+g: conflict-free)
#define SMEM_FLOATS (STAGES*(TM*A_STRIDE + TKK*B_STRIDE))
#define SMEM_BYTES (SMEM_FLOATS*4 + TM*4)

__device__ __forceinline__ float gelu_tanh(float v) {
    float c = v * v * v;
    return 0.5f * v * (1.f + tanhf(0.7978845608028654f * (v + 0.044715f * c)));
}

__device__ __forceinline__ void mma_tf32(float* c, const uint32_t* a, const uint32_t* b) {
    asm volatile(
        "mma.sync.aligned.m16n8k8.row.col.f32.tf32.tf32.f32 "
        "{%0,%1,%2,%3}, {%4,%5,%6,%7}, {%8,%9}, {%0,%1,%2,%3};"
        : "+f"(c[0]), "+f"(c[1]), "+f"(c[2]), "+f"(c[3])
        : "r"(a[0]), "r"(a[1]), "r"(a[2]), "r"(a[3]), "r"(b[0]), "r"(b[1]));
}

__device__ __forceinline__ void cp_async16(float* dst, const float* src, bool pred) {
    uint32_t d = (uint32_t)__cvta_generic_to_shared(dst);
    int sz = pred ? 16 : 0;
    asm volatile("cp.async.cg.shared.global [%0], [%1], 16, %2;\n"
                 :: "r"(d), "l"(src), "r"(sz));
}

// UP:  A = gathered g_xr rows, W = g_wur[e] (DIM x HID), epilogue = gelu+round -> g_h
// DN:  A = gathered g_h rows,  W = g_wdr[e] (HID x DIM), epilogue = +bias -> g_y
// All GEMM inputs are pre-rounded to tf32: the mainloop has NO cvt instructions.
template<bool UP>
__global__ __launch_bounds__(128)
void mma_gemm_kernel(const float* __restrict__ Ball)
{
    constexpr int KD = UP ? DIM : HID;
    constexpr int ND = UP ? HID : DIM;
    constexpr int KT = KD / TKK;

    int e   = blockIdx.z;
    int cnt = g_cursor[e];
    int m0  = blockIdx.y * TM;
    if (m0 >= cnt) return;
    int n0  = blockIdx.x * TN;

    extern __shared__ float smem[];
    float* As = smem;                                   // [STAGES][TM][A_STRIDE]
    float* Bs = smem + STAGES * TM * A_STRIDE;          // [STAGES][TKK][B_STRIDE]
    int*  rows = (int*)(Bs + STAGES * TKK * B_STRIDE);  // [TM]

    int tid = threadIdx.x;
    for (int i = tid; i < TM; i += 128) {
        int m = m0 + i;
        rows[i] = (m < cnt) ? g_bucket[e * CAP + m] : -1;
    }
    __syncthreads();

    const float* W = (UP ? g_wur : g_wdr) + (size_t)e * KD * ND;
    const float* Abase = UP ? (const float*)g_xr : (const float*)g_h;

    auto issue = [&](int kt, int stage) {
        float* as = As + stage * TM * A_STRIDE;
        float* bs = Bs + stage * TKK * B_STRIDE;
        int kbase = kt * TKK;
        #pragma unroll
        for (int i = 0; i < 8; i++) {
            int c = tid + i * 128;
            int r = c >> 3, q = c & 7;      // 128 rows x 8 float4 chunks
            int a = rows[r];
            bool pred = (a >= 0);
            const float* src;
            if (UP) src = Abase + (size_t)(pred ? (a >> 1) : 0) * DIM + kbase + q * 4;
            else    src = Abase + (size_t)(pred ? a : 0) * HID + kbase + q * 4;
            cp_async16(as + r * A_STRIDE + q * 4, src, pred);
        }
        #pragma unroll
        for (int i = 0; i < 8; i++) {
            int c = tid + i * 128;
            int k = c >> 5, q = c & 31;     // 32 k-rows x 32 float4 chunks
            cp_async16(bs + k * B_STRIDE + q * 4,
                       W + (size_t)(kbase + k) * ND + n0 + q * 4, true);
        }
    };

    #pragma unroll
    for (int s = 0; s < STAGES - 1; s++) {
        if (s < KT) issue(s, s);
        asm volatile("cp.async.commit_group;");
    }

    int wid = tid >> 5, lane = tid & 31;
    int g = lane >> 2, t = lane & 3;
    int wm = (wid >> 1) * 64;   // 2x2 warp grid, 64x64 warp tiles
    int wn = (wid & 1) * 64;

    float acc[4][8][4];
    #pragma unroll
    for (int i = 0; i < 4; i++)
        #pragma unroll
        for (int j = 0; j < 8; j++)
            #pragma unroll
            for (int q = 0; q < 4; q++) acc[i][j][q] = 0.f;

    for (int kt = 0; kt < KT; kt++) {
        asm volatile("cp.async.wait_group %0;" :: "n"(STAGES - 2));
        __syncthreads();

        int nstage = kt + STAGES - 1;
        if (nstage < KT) issue(nstage, nstage % STAGES);
        asm volatile("cp.async.commit_group;");

        const uint32_t* as = (const uint32_t*)(As + (kt % STAGES) * TM * A_STRIDE);
        const uint32_t* bs = (const uint32_t*)(Bs + (kt % STAGES) * TKK * B_STRIDE);

        #pragma unroll
        for (int k8 = 0; k8 < TKK / 8; k8++) {
            uint32_t af[4][4], bf[8][2];
            #pragma unroll
            for (int i = 0; i < 4; i++) {
                int mrow = wm + i * 16;
                af[i][0] = as[(mrow + g    ) * A_STRIDE + k8 * 8 + t];
                af[i][1] = as[(mrow + g + 8) * A_STRIDE + k8 * 8 + t];
                af[i][2] = as[(mrow + g    ) * A_STRIDE + k8 * 8 + t + 4];
                af[i][3] = as[(mrow + g + 8) * A_STRIDE + k8 * 8 + t + 4];
            }
            #pragma unroll
            for (int j = 0; j < 8; j++) {
                int ncol = wn + j * 8 + g;
                bf[j][0] = bs[(k8 * 8 + t    ) * B_STRIDE + ncol];
                bf[j][1] = bs[(k8 * 8 + t + 4) * B_STRIDE + ncol];
            }
            #pragma unroll
            for (int i = 0; i < 4; i++)
                #pragma unroll
                for (int j = 0; j < 8; j++)
                    mma_tf32(acc[i][j], af[i], bf[j]);
        }
    }

    // epilogue: bias (+gelu, +tf32 round for UP) and scatter by assignment id
    const float* bb = Ball + (size_t)e * ND + n0;
    #pragma unroll
    for (int i = 0; i < 4; i++) {
        int r0 = wm + i * 16 + g;
        int r1 = r0 + 8;
        int a0 = rows[r0], a1 = rows[r1];
        float* d0 = (a0 >= 0) ? ((UP ? g_h + (size_t)a0 * HID : g_y + (size_t)a0 * DIM) + n0) : nullptr;
        float* d1 = (a1 >= 0) ? ((UP ? g_h + (size_t)a1 * HID : g_y + (size_t)a1 * DIM) + n0) : nullptr;
        #pragma unroll
        for (int j = 0; j < 8; j++) {
            int col = wn + j * 8 + t * 2;
            float bx = bb[col], by = bb[col + 1];
            if (d0) {
                float v0 = acc[i][j][0] + bx, v1 = acc[i][j][1] + by;
                if (UP) {
                    v0 = __uint_as_float(f2tf32(gelu_tanh(v0)));
                    v1 = __uint_as_float(f2tf32(gelu_tanh(v1)));
                }
                *(float2*)(d0 + col) = make_float2(v0, v1);
            }
            if (d1) {
                float v2 = acc[i][j][2] + bx, v3 = acc[i][j][3] + by;
                if (UP) {
                    v2 = __uint_as_float(f2tf32(gelu_tanh(v2)));
                    v3 = __uint_as_float(f2tf32(gelu_tanh(v3)));
                }
                *(float2*)(d1 + col) = make_float2(v2, v3);
            }
        }
    }
}

// ---------------- kernel 6: deterministic weighted combine ----------------
__global__ __launch_bounds__(256) void combine_kernel(float* __restrict__ out) {
    int t = blockIdx.x;
    float w0 = g_topk_w[t * TOPK + 0];
    float w1 = g_topk_w[t * TOPK + 1];
    const float4* y0 = (const float4*)(g_y + (size_t)(t * TOPK + 0) * DIM);
    const float4* y1 = (const float4*)(g_y + (size_t)(t * TOPK + 1) * DIM);
    float4* o = (float4*)(out + (size_t)t * DIM);
    for (int d = threadIdx.x; d < DIM / 4; d += 256) {
        float4 a = y0[d], b = y1[d];
        float4 r;
        r.x = w0 * a.x + w1 * b.x;
        r.y = w0 * a.y + w1 * b.y;
        r.z = w0 * a.z + w1 * b.z;
        r.w = w0 * a.w + w1 * b.w;
        o[d] = r;
    }
}

// ---------------- launch ----------------
extern "C" void kernel_launch(void* const* d_in, const int* in_sizes, int n_in,
                              void* d_out, int out_size)
{
    const float* x  = (const float*)d_in[0];
    const float* rw = (const float*)d_in[1];
    const float* rb = (const float*)d_in[2];
    const float* wu = (const float*)d_in[3];
    const float* bu = (const float*)d_in[4];
    const float* wd = (const float*)d_in[5];
    const float* bd = (const float*)d_in[6];

    float* out       = (float*)d_out;
    float* out_y     = out;
    float* out_aux   = out + (size_t)NTOK * DIM;
    float* out_probs = out_aux + 1;

    cudaFuncSetAttribute(mma_gemm_kernel<true>,
        cudaFuncAttributeMaxDynamicSharedMemorySize, SMEM_BYTES);
    cudaFuncSetAttribute(mma_gemm_kernel<false>,
        cudaFuncAttributeMaxDynamicSharedMemorySize, SMEM_BYTES);

    float* d_xr  = nullptr; cudaGetSymbolAddress((void**)&d_xr,  g_xr);
    float* d_wur = nullptr; cudaGetSymbolAddress((void**)&d_wur, g_wur);
    float* d_wdr = nullptr; cudaGetSymbolAddress((void**)&d_wdr, g_wdr);

    zero_kernel<<<1, 32>>>();
    router_kernel<<<NTOK, 256>>>(x, rw, rb, out_probs);
    aux_kernel<<<1, 32>>>(out_aux);

    // tf32 pre-round (one-time cvt per element)
    round_kernel<<<1184, 256>>>((const float4*)x,  (float4*)d_xr,  NTOK * DIM / 4);
    round_kernel<<<2368, 256>>>((const float4*)wu, (float4*)d_wur, NE * DIM * HID / 4);
    round_kernel<<<2368, 256>>>((const float4*)wd, (float4*)d_wdr, NE * HID * DIM / 4);

    dim3 gu(HID / TN, CAP / TM, NE);
    mma_gemm_kernel<true><<<gu, 128, SMEM_BYTES>>>(bu);

    dim3 gd(DIM / TN, CAP / TM, NE);
    mma_gemm_kernel<false><<<gd, 128, SMEM_BYTES>>>(bd);

    combine_kernel<<<NTOK, 256>>>(out_y);
}

// round 5
// speedup vs baseline: 3.5769x; 1.0079x over previous
#include <cuda_runtime.h>
#include <math.h>
#include <cstdint>

#define NTOK 8192      // B*S
#define DIM  1024      // d_model
#define NE   8         // experts
#define TOPK 2
#define HID  4096      // expert hidden
#define NA   (NTOK*TOPK)   // 16384 assignments
#define CAP  NA            // per-expert bucket capacity (worst case)

// ---------------- device scratch (no allocations allowed) ----------------
__device__ int   g_bucket[NE*CAP];
__device__ int   g_cursor[NE];
__device__ float g_prob_sum[NE];
__device__ float g_topk_w[NA];
__device__ float g_h[(size_t)NA*HID];       // up-proj activations (268 MB), tf32-rounded
__device__ float g_y[(size_t)NA*DIM];       // down-proj outputs   (67 MB)
__device__ float g_xr[(size_t)NTOK*DIM];    // tf32-rounded x      (33 MB)
__device__ float g_wur[(size_t)NE*DIM*HID]; // tf32-rounded w_up   (134 MB)
__device__ float g_wdr[(size_t)NE*HID*DIM]; // tf32-rounded w_down (134 MB)

__device__ __forceinline__ uint32_t f2tf32(float f) {
    uint32_t r;
    asm("cvt.rna.tf32.f32 %0, %1;" : "=r"(r) : "f"(f));
    return r;
}

// ---------------- tf32 pre-round (one cvt per element, outside GEMM) ------
__global__ __launch_bounds__(256) void round_kernel(
    const float4* __restrict__ src, float4* __restrict__ dst, int n4)
{
    int stride = gridDim.x * blockDim.x;
    for (int i = blockIdx.x * blockDim.x + threadIdx.x; i < n4; i += stride) {
        float4 v = src[i];
        v.x = __uint_as_float(f2tf32(v.x));
        v.y = __uint_as_float(f2tf32(v.y));
        v.z = __uint_as_float(f2tf32(v.z));
        v.w = __uint_as_float(f2tf32(v.w));
        dst[i] = v;
    }
}

// ---------------- kernel 1: zero accumulators ----------------
__global__ void zero_kernel() {
    int t = threadIdx.x;
    if (t < NE) { g_cursor[t] = 0; g_prob_sum[t] = 0.f; }
}

// ---------------- kernel 2: router ----------------
__global__ __launch_bounds__(256) void router_kernel(
    const float* __restrict__ x, const float* __restrict__ rw,
    const float* __restrict__ rb, float* __restrict__ probs_out)
{
    int t   = blockIdx.x;
    int tid = threadIdx.x;
    const float* xr = x + (size_t)t * DIM;

    float acc[NE];
    #pragma unroll
    for (int e = 0; e < NE; e++) acc[e] = 0.f;

    for (int d = tid; d < DIM; d += 256) {
        float xv = xr[d];
        const float* w = rw + (size_t)d * NE;
        #pragma unroll
        for (int e = 0; e < NE; e++) acc[e] += xv * w[e];
    }
    #pragma unroll
    for (int e = 0; e < NE; e++) {
        #pragma unroll
        for (int off = 16; off > 0; off >>= 1)
            acc[e] += __shfl_down_sync(0xffffffffu, acc[e], off);
    }
    __shared__ float wsum[8][NE];
    int warp = tid >> 5, lane = tid & 31;
    if (lane == 0) {
        #pragma unroll
        for (int e = 0; e < NE; e++) wsum[warp][e] = acc[e];
    }
    __syncthreads();

    if (tid == 0) {
        float lg[NE];
        #pragma unroll
        for (int e = 0; e < NE; e++) {
            float s = rb[e];
            #pragma unroll
            for (int w = 0; w < 8; w++) s += wsum[w][e];
            lg[e] = s;
        }
        float mx = lg[0];
        #pragma unroll
        for (int e = 1; e < NE; e++) mx = fmaxf(mx, lg[e]);
        float p[NE], den = 0.f;
        #pragma unroll
        for (int e = 0; e < NE; e++) { p[e] = expf(lg[e] - mx); den += p[e]; }
        float inv = 1.f / den;
        #pragma unroll
        for (int e = 0; e < NE; e++) {
            p[e] *= inv;
            probs_out[(size_t)t * NE + e] = p[e];
            atomicAdd(&g_prob_sum[e], p[e]);
        }
        int i0 = 0;
        #pragma unroll
        for (int e = 1; e < NE; e++) if (lg[e] > lg[i0]) i0 = e;
        int i1 = -1;
        #pragma unroll
        for (int e = 0; e < NE; e++)
            if (e != i0 && (i1 < 0 || lg[e] > lg[i1])) i1 = e;
        float e1 = expf(lg[i1] - lg[i0]);
        float p0 = 1.f / (1.f + e1);
        float p1 = e1 * p0;

        int a0 = t * TOPK + 0, a1 = t * TOPK + 1;
        g_topk_w[a0] = p0;
        g_topk_w[a1] = p1;
        int s0 = atomicAdd(&g_cursor[i0], 1);
        g_bucket[i0 * CAP + s0] = a0;
        int s1 = atomicAdd(&g_cursor[i1], 1);
        g_bucket[i1 * CAP + s1] = a1;
    }
}

// ---------------- kernel 3: aux loss ----------------
__global__ void aux_kernel(float* __restrict__ out_aux) {
    if (threadIdx.x == 0) {
        float s = 0.f;
        #pragma unroll
        for (int e = 0; e < NE; e++)
            s += ((float)g_cursor[e] / (float)NA) * (g_prob_sum[e] / (float)NTOK);
        *out_aux = (float)NE * s * 0.01f;
    }
}

// ---------------- tensor-core grouped GEMM ----------------
// 256 threads (8 warps, 4x2 grid of 32x64 warp tiles), 2 CTAs/SM.
#define TM 128
#define TN 128
#define TKK 32
#define STAGES 3
#define A_STRIDE (TKK+4)     // A tile [m][k]
#define B_STRIDE (TN+8)      // B tile [k][n]
#define SMEM_FLOATS (STAGES*(TM*A_STRIDE + TKK*B_STRIDE))
#define SMEM_BYTES (SMEM_FLOATS*4 + TM*4)

__device__ __forceinline__ float gelu_tanh(float v) {
    float c = v * v * v;
    return 0.5f * v * (1.f + tanhf(0.7978845608028654f * (v + 0.044715f * c)));
}

__device__ __forceinline__ void mma_tf32(float* c, const uint32_t* a, const uint32_t* b) {
    asm volatile(
        "mma.sync.aligned.m16n8k8.row.col.f32.tf32.tf32.f32 "
        "{%0,%1,%2,%3}, {%4,%5,%6,%7}, {%8,%9}, {%0,%1,%2,%3};"
        : "+f"(c[0]), "+f"(c[1]), "+f"(c[2]), "+f"(c[3])
        : "r"(a[0]), "r"(a[1]), "r"(a[2]), "r"(a[3]), "r"(b[0]), "r"(b[1]));
}

__device__ __forceinline__ void cp_async16(float* dst, const float* src, bool pred) {
    uint32_t d = (uint32_t)__cvta_generic_to_shared(dst);
    int sz = pred ? 16 : 0;
    asm volatile("cp.async.cg.shared.global [%0], [%1], 16, %2;\n"
                 :: "r"(d), "l"(src), "r"(sz));
}

// UP:  A = gathered g_xr rows, W = g_wur[e] (DIM x HID), epilogue = gelu+round -> g_h
// DN:  A = gathered g_h rows,  W = g_wdr[e] (HID x DIM), epilogue = +bias -> g_y
template<bool UP>
__global__ __launch_bounds__(256, 2)
void mma_gemm_kernel(const float* __restrict__ Ball)
{
    constexpr int KD = UP ? DIM : HID;
    constexpr int ND = UP ? HID : DIM;
    constexpr int KT = KD / TKK;

    int e   = blockIdx.z;
    int cnt = g_cursor[e];
    int m0  = blockIdx.y * TM;
    if (m0 >= cnt) return;
    int n0  = blockIdx.x * TN;

    extern __shared__ float smem[];
    float* As = smem;                                   // [STAGES][TM][A_STRIDE]
    float* Bs = smem + STAGES * TM * A_STRIDE;          // [STAGES][TKK][B_STRIDE]
    int*  rows = (int*)(Bs + STAGES * TKK * B_STRIDE);  // [TM]

    int tid = threadIdx.x;
    if (tid < TM) {
        int m = m0 + tid;
        rows[tid] = (m < cnt) ? g_bucket[e * CAP + m] : -1;
    }
    __syncthreads();

    const float* W = (UP ? g_wur : g_wdr) + (size_t)e * KD * ND;
    const float* Abase = UP ? (const float*)g_xr : (const float*)g_h;

    auto issue = [&](int kt, int stage) {
        float* as = As + stage * TM * A_STRIDE;
        float* bs = Bs + stage * TKK * B_STRIDE;
        int kbase = kt * TKK;
        #pragma unroll
        for (int i = 0; i < 4; i++) {
            int c = tid + i * 256;
            int r = c >> 3, q = c & 7;      // 128 rows x 8 float4 chunks
            int a = rows[r];
            bool pred = (a >= 0);
            const float* src;
            if (UP) src = Abase + (size_t)(pred ? (a >> 1) : 0) * DIM + kbase + q * 4;
            else    src = Abase + (size_t)(pred ? a : 0) * HID + kbase + q * 4;
            cp_async16(as + r * A_STRIDE + q * 4, src, pred);
        }
        #pragma unroll
        for (int i = 0; i < 4; i++) {
            int c = tid + i * 256;
            int k = c >> 5, q = c & 31;     // 32 k-rows x 32 float4 chunks
            cp_async16(bs + k * B_STRIDE + q * 4,
                       W + (size_t)(kbase + k) * ND + n0 + q * 4, true);
        }
    };

    #pragma unroll
    for (int s = 0; s < STAGES - 1; s++) {
        if (s < KT) issue(s, s);
        asm volatile("cp.async.commit_group;");
    }

    int wid = tid >> 5, lane = tid & 31;
    int g = lane >> 2, t = lane & 3;
    int wm = (wid >> 1) * 32;   // 4x2 warp grid, 32x64 warp tiles
    int wn = (wid & 1) * 64;

    float acc[2][8][4];
    #pragma unroll
    for (int i = 0; i < 2; i++)
        #pragma unroll
        for (int j = 0; j < 8; j++)
            #pragma unroll
            for (int q = 0; q < 4; q++) acc[i][j][q] = 0.f;

    for (int kt = 0; kt < KT; kt++) {
        asm volatile("cp.async.wait_group %0;" :: "n"(STAGES - 2));
        __syncthreads();

        int nstage = kt + STAGES - 1;
        if (nstage < KT) issue(nstage, nstage % STAGES);
        asm volatile("cp.async.commit_group;");

        const uint32_t* as = (const uint32_t*)(As + (kt % STAGES) * TM * A_STRIDE);
        const uint32_t* bs = (const uint32_t*)(Bs + (kt % STAGES) * TKK * B_STRIDE);

        #pragma unroll
        for (int k8 = 0; k8 < TKK / 8; k8++) {
            uint32_t af[2][4], bf[8][2];
            #pragma unroll
            for (int i = 0; i < 2; i++) {
                int mrow = wm + i * 16;
                af[i][0] = as[(mrow + g    ) * A_STRIDE + k8 * 8 + t];
                af[i][1] = as[(mrow + g + 8) * A_STRIDE + k8 * 8 + t];
                af[i][2] = as[(mrow + g    ) * A_STRIDE + k8 * 8 + t + 4];
                af[i][3] = as[(mrow + g + 8) * A_STRIDE + k8 * 8 + t + 4];
            }
            #pragma unroll
            for (int j = 0; j < 8; j++) {
                int ncol = wn + j * 8 + g;
                bf[j][0] = bs[(k8 * 8 + t    ) * B_STRIDE + ncol];
                bf[j][1] = bs[(k8 * 8 + t + 4) * B_STRIDE + ncol];
            }
            #pragma unroll
            for (int i = 0; i < 2; i++)
                #pragma unroll
                for (int j = 0; j < 8; j++)
                    mma_tf32(acc[i][j], af[i], bf[j]);
        }
    }

    // epilogue: bias (+gelu, +tf32 round for UP) and scatter by assignment id
    const float* bb = Ball + (size_t)e * ND + n0;
    #pragma unroll
    for (int i = 0; i < 2; i++) {
        int r0 = wm + i * 16 + g;
        int r1 = r0 + 8;
        int a0 = rows[r0], a1 = rows[r1];
        float* d0 = (a0 >= 0) ? ((UP ? g_h + (size_t)a0 * HID : g_y + (size_t)a0 * DIM) + n0) : nullptr;
        float* d1 = (a1 >= 0) ? ((UP ? g_h + (size_t)a1 * HID : g_y + (size_t)a1 * DIM) + n0) : nullptr;
        #pragma unroll
        for (int j = 0; j < 8; j++) {
            int col = wn + j * 8 + t * 2;
            float bx = bb[col], by = bb[col + 1];
            if (d0) {
                float v0 = acc[i][j][0] + bx, v1 = acc[i][j][1] + by;
                if (UP) {
                    v0 = __uint_as_float(f2tf32(gelu_tanh(v0)));
                    v1 = __uint_as_float(f2tf32(gelu_tanh(v1)));
                }
                *(float2*)(d0 + col) = make_float2(v0, v1);
            }
            if (d1) {
                float v2 = acc[i][j][2] + bx, v3 = acc[i][j][3] + by;
                if (UP) {
                    v2 = __uint_as_float(f2tf32(gelu_tanh(v2)));
                    v3 = __uint_as_float(f2tf32(gelu_tanh(v3)));
                }
                *(float2*)(d1 + col) = make_float2(v2, v3);
            }
        }
    }
}

// ---------------- kernel 6: deterministic weighted combine ----------------
__global__ __launch_bounds__(256) void combine_kernel(float* __restrict__ out) {
    int t = blockIdx.x;
    float w0 = g_topk_w[t * TOPK + 0];
    float w1 = g_topk_w[t * TOPK + 1];
    const float4* y0 = (const float4*)(g_y + (size_t)(t * TOPK + 0) * DIM);
    const float4* y1 = (const float4*)(g_y + (size_t)(t * TOPK + 1) * DIM);
    float4* o = (float4*)(out + (size_t)t * DIM);
    for (int d = threadIdx.x; d < DIM / 4; d += 256) {
        float4 a = y0[d], b = y1[d];
        float4 r;
        r.x = w0 * a.x + w1 * b.x;
        r.y = w0 * a.y + w1 * b.y;
        r.z = w0 * a.z + w1 * b.z;
        r.w = w0 * a.w + w1 * b.w;
        o[d] = r;
    }
}

// ---------------- launch ----------------
extern "C" void kernel_launch(void* const* d_in, const int* in_sizes, int n_in,
                              void* d_out, int out_size)
{
    const float* x  = (const float*)d_in[0];
    const float* rw = (const float*)d_in[1];
    const float* rb = (const float*)d_in[2];
    const float* wu = (const float*)d_in[3];
    const float* bu = (const float*)d_in[4];
    const float* wd = (const float*)d_in[5];
    const float* bd = (const float*)d_in[6];

    float* out       = (float*)d_out;
    float* out_y     = out;
    float* out_aux   = out + (size_t)NTOK * DIM;
    float* out_probs = out_aux + 1;

    cudaFuncSetAttribute(mma_gemm_kernel<true>,
        cudaFuncAttributeMaxDynamicSharedMemorySize, SMEM_BYTES);
    cudaFuncSetAttribute(mma_gemm_kernel<false>,
        cudaFuncAttributeMaxDynamicSharedMemorySize, SMEM_BYTES);

    float* d_xr  = nullptr; cudaGetSymbolAddress((void**)&d_xr,  g_xr);
    float* d_wur = nullptr; cudaGetSymbolAddress((void**)&d_wur, g_wur);
    float* d_wdr = nullptr; cudaGetSymbolAddress((void**)&d_wdr, g_wdr);

    zero_kernel<<<1, 32>>>();
    router_kernel<<<NTOK, 256>>>(x, rw, rb, out_probs);
    aux_kernel<<<1, 32>>>(out_aux);

    // tf32 pre-round (one-time cvt per element)
    round_kernel<<<1184, 256>>>((const float4*)x,  (float4*)d_xr,  NTOK * DIM / 4);
    round_kernel<<<2368, 256>>>((const float4*)wu, (float4*)d_wur, NE * DIM * HID / 4);
    round_kernel<<<2368, 256>>>((const float4*)wd, (float4*)d_wdr, NE * HID * DIM / 4);

    dim3 gu(HID / TN, CAP / TM, NE);
    mma_gemm_kernel<true><<<gu, 256, SMEM_BYTES>>>(bu);

    dim3 gd(DIM / TN, CAP / TM, NE);
    mma_gemm_kernel<false><<<gd, 256, SMEM_BYTES>>>(bd);

    combine_kernel<<<NTOK, 256>>>(out_y);
}